// round 9
// baseline (speedup 1.0000x reference)
#include <cuda_runtime.h>
#include <cuda_fp16.h>
#include <cstdint>

// ---------------------------------------------------------------------------
// EdgeDecoder:
//   A'[n] = z[n] @ W1[0:128,:] + b1 ; B[n] = z[n] @ W1[128:256,:]
//   score[e] = relu(A'[src] + B[dst]) . W2 + b2
//
// Kernel 0 (prep): W1 -> fp16 fused [128][256] layout + dtype probe.
// Kernel 1 (gemm): persistent, M-tile 64, 2 CTAs/SM, 2-term compensated HMMA.
// Kernel 2 (edge): warp batches 16 edges. Gather + half2 add/relu (proven R6
//   pattern) -> fp16 H tile in smem -> ldsm + mma.m16n8k16 does the 128-dot
//   against W2 (hi+lo compensated) with fp32 accum. Replaces per-edge
//   F2F/FFMA/SHFL reduction (~10 warp-instr/edge saved).
// ---------------------------------------------------------------------------

#define HID 128
#define N_MAX 100000

__device__ __align__(16) __half g_AB[(size_t)N_MAX * 256];
__device__ __align__(16) __half g_Whi[128 * 256];
__device__ int g_is64;

// ---- tensor-core primitives ----
__device__ __forceinline__ void ldsm4(unsigned* r, const void* p) {
    unsigned a = (unsigned)__cvta_generic_to_shared(p);
    asm volatile("ldmatrix.sync.aligned.m8n8.x4.shared.b16 {%0,%1,%2,%3},[%4];"
                 : "=r"(r[0]), "=r"(r[1]), "=r"(r[2]), "=r"(r[3]) : "r"(a));
}
__device__ __forceinline__ void ldsm2t(unsigned* r, const void* p) {
    unsigned a = (unsigned)__cvta_generic_to_shared(p);
    asm volatile("ldmatrix.sync.aligned.m8n8.x2.trans.shared.b16 {%0,%1},[%2];"
                 : "=r"(r[0]), "=r"(r[1]) : "r"(a));
}
__device__ __forceinline__ void stsm4(void* p, unsigned r0, unsigned r1,
                                      unsigned r2, unsigned r3) {
    unsigned a = (unsigned)__cvta_generic_to_shared(p);
    asm volatile("stmatrix.sync.aligned.m8n8.x4.shared.b16 [%0],{%1,%2,%3,%4};"
                 :: "r"(a), "r"(r0), "r"(r1), "r"(r2), "r"(r3));
}
__device__ __forceinline__ void mma16816(float* c, const unsigned* a, const unsigned* b) {
    asm volatile(
        "mma.sync.aligned.m16n8k16.row.col.f32.f16.f16.f32 "
        "{%0,%1,%2,%3},{%4,%5,%6,%7},{%8,%9},{%0,%1,%2,%3};"
        : "+f"(c[0]), "+f"(c[1]), "+f"(c[2]), "+f"(c[3])
        : "r"(a[0]), "r"(a[1]), "r"(a[2]), "r"(a[3]), "r"(b[0]), "r"(b[1]));
}

// smem strides in halves; padded -> conflict-free ldmatrix
#define ZS 136
#define WS 264
#define OS 264
#define MTILE 64
#define SMEM_BYTES ((128 * WS + 2 * MTILE * ZS) * 2)   // 102,400 B -> 2 CTAs/SM

// ---------------------------------------------------------------------------
__global__ __launch_bounds__(512) void prep_w(
    const float* __restrict__ W1, const int* __restrict__ ei32)
{
    if (blockIdx.x == 0 && threadIdx.x == 0) {
        int all0 = 1;
#pragma unroll
        for (int i = 0; i < 8; ++i) all0 &= (ei32[2 * i + 1] == 0);
        g_is64 = all0;
    }
    int idx = blockIdx.x * 512 + threadIdx.x;   // grid 64 -> 32768
    int k = idx >> 8, j = idx & 255;
    float f = (j < 128) ? W1[(size_t)k * 128 + j]
                        : W1[(size_t)(128 + k) * 128 + (j - 128)];
    g_Whi[idx] = __float2half_rn(f);
}

// ---------------------------------------------------------------------------
// Persistent GEMM (R8): M-tile 64, 2 CTAs/SM, 2-term compensated.
// ---------------------------------------------------------------------------
__global__ __launch_bounds__(512, 2) void gemm_tc(
    const float* __restrict__ z, const float* __restrict__ b1,
    int N, int nstrips)
{
    extern __shared__ __align__(16) char dynsmem[];
    __half* Whi = (__half*)dynsmem;            // [128][WS]
    __half* Zhi = Whi + 128 * WS;              // [MTILE][ZS]
    __half* Zlo = Zhi + MTILE * ZS;
    __half* Stage = Zhi;                       // overlay [MTILE][OS]

    const int t    = threadIdx.x;
    const int lane = t & 31;
    const int w    = t >> 5;

#pragma unroll
    for (int i = 0; i < 8; ++i) {
        int idx = t + i * 512;
        int row = idx >> 5, c16 = idx & 31;
        *(uint4*)&Whi[row * WS + c16 * 8] = *(const uint4*)&g_Whi[row * 256 + c16 * 8];
    }
    __syncthreads();

    const int wm = w >> 3, wn = w & 7;
    const int mbase = wm * 32, nbase = wn * 32;
    const int arow = lane & 15, acol8 = (lane >> 4) << 3;
    const int brow = lane & 15;

    float bx[4], by[4];
#pragma unroll
    for (int nt = 0; nt < 4; ++nt) {
        int col = nbase + nt * 8 + (lane & 3) * 2;
        bx[nt] = (wn < 4) ? __ldg(b1 + col)     : 0.f;
        by[nt] = (wn < 4) ? __ldg(b1 + col + 1) : 0.f;
    }

    for (int strip = blockIdx.x; strip < nstrips; strip += gridDim.x) {
        const int row0 = strip * MTILE;

#pragma unroll
        for (int i = 0; i < 4; ++i) {
            int idx4 = t + i * 512;
            int r = idx4 >> 5, c = (idx4 & 31) * 4;
            int gr = row0 + r; if (gr >= N) gr = N - 1;
            float4 v = *(const float4*)(z + (size_t)gr * HID + c);
            __half2 h0 = __floats2half2_rn(v.x, v.y);
            __half2 h1 = __floats2half2_rn(v.z, v.w);
            float2 f0 = __half22float2(h0), f1 = __half22float2(h1);
            __half2 l0 = __floats2half2_rn(v.x - f0.x, v.y - f0.y);
            __half2 l1 = __floats2half2_rn(v.z - f1.x, v.w - f1.y);
            uint2 sh, sl;
            sh.x = *(unsigned*)&h0; sh.y = *(unsigned*)&h1;
            sl.x = *(unsigned*)&l0; sl.y = *(unsigned*)&l1;
            *(uint2*)&Zhi[r * ZS + c] = sh;
            *(uint2*)&Zlo[r * ZS + c] = sl;
        }
        __syncthreads();

        float acc[2][4][4];
#pragma unroll
        for (int mt = 0; mt < 2; ++mt)
#pragma unroll
            for (int nt = 0; nt < 4; ++nt)
#pragma unroll
                for (int q = 0; q < 4; ++q) acc[mt][nt][q] = 0.f;

#pragma unroll
        for (int ks = 0; ks < 8; ++ks) {
            const int k0 = ks * 16;
            unsigned ah[2][4], al[2][4];
#pragma unroll
            for (int mt = 0; mt < 2; ++mt) {
                const int rr = (mbase + mt * 16 + arow) * ZS + k0 + acol8;
                ldsm4(ah[mt], Zhi + rr);
                ldsm4(al[mt], Zlo + rr);
            }
#pragma unroll
            for (int nt = 0; nt < 4; ++nt) {
                unsigned bb[2];
                const int wr = (k0 + brow) * WS + nbase + nt * 8;
                ldsm2t(bb, Whi + wr);
#pragma unroll
                for (int mt = 0; mt < 2; ++mt) {
                    mma16816(acc[mt][nt], ah[mt], bb);
                    mma16816(acc[mt][nt], al[mt], bb);
                }
            }
        }
        __syncthreads();

        const int stile = lane >> 3;
        const int srow  = lane & 7;
#pragma unroll
        for (int mt = 0; mt < 2; ++mt) {
            __half2 u[4], l[4];
#pragma unroll
            for (int nt = 0; nt < 4; ++nt) {
                u[nt] = __floats2half2_rn(acc[mt][nt][0] + bx[nt], acc[mt][nt][1] + by[nt]);
                l[nt] = __floats2half2_rn(acc[mt][nt][2] + bx[nt], acc[mt][nt][3] + by[nt]);
            }
            __half* pu = Stage + (mbase + mt * 16 + srow) * OS + nbase + stile * 8;
            __half* pl = Stage + (mbase + mt * 16 + 8 + srow) * OS + nbase + stile * 8;
            stsm4(pu, *(unsigned*)&u[0], *(unsigned*)&u[1], *(unsigned*)&u[2], *(unsigned*)&u[3]);
            stsm4(pl, *(unsigned*)&l[0], *(unsigned*)&l[1], *(unsigned*)&l[2], *(unsigned*)&l[3]);
        }
        __syncthreads();

#pragma unroll
        for (int i = 0; i < 4; ++i) {
            int idx = t + i * 512;
            int r = idx >> 5, c16 = idx & 31;
            int gr = row0 + r;
            if (gr < N) {
                uint4 v = *(const uint4*)&Stage[r * OS + c16 * 8];
                *(uint4*)&g_AB[(size_t)gr * 256 + c16 * 8] = v;
            }
        }
        __syncthreads();
    }
}

// ---------------------------------------------------------------------------
// Edge kernel: warp batches 16 edges; gather+relu -> smem fp16 H tile;
// mma m16n8k16 vs W2 (hi+lo) does the 128-dot with fp32 accumulation.
// ---------------------------------------------------------------------------
#define HS 136   // H tile row stride in halves

__global__ __launch_bounds__(256) void edge_score(
    const void* __restrict__ ei_raw,   // [2,E] int32 or int64 (g_is64)
    const float* __restrict__ W2,      // [128]
    const float* __restrict__ b2,      // [1]
    float* __restrict__ out,           // [E]
    int E, int N)
{
    __shared__ __align__(16) __half Hs[8 * 16 * HS];   // 8 warps x 16 rows

    const int lane = threadIdx.x & 31;
    const int gl   = lane & 15;
    const int hi16 = lane >> 4;                 // 0/1: which edge of the pair
    const int warp = threadIdx.x >> 5;
    const int wbase = (blockIdx.x * 8 + warp) * 16;    // first edge of batch
    __half* H = Hs + warp * 16 * HS;

    // ---- W2 fragments: col-major B-frag, all 8 cols = W2; hi + lo split ----
    const int m = lane & 3;
    unsigned w2h[8][2], w2l[8][2];
#pragma unroll
    for (int kc = 0; kc < 8; ++kc) {
        float f0 = __ldg(W2 + kc * 16 + 2 * m);
        float f1 = __ldg(W2 + kc * 16 + 2 * m + 1);
        float f2 = __ldg(W2 + kc * 16 + 8 + 2 * m);
        float f3 = __ldg(W2 + kc * 16 + 8 + 2 * m + 1);
        __half2 h0 = __floats2half2_rn(f0, f1);
        __half2 h1 = __floats2half2_rn(f2, f3);
        float2 g0 = __half22float2(h0), g1 = __half22float2(h1);
        __half2 l0 = __floats2half2_rn(f0 - g0.x, f1 - g0.y);
        __half2 l1 = __floats2half2_rn(f2 - g1.x, f3 - g1.y);
        w2h[kc][0] = *(unsigned*)&h0; w2h[kc][1] = *(unsigned*)&h1;
        w2l[kc][0] = *(unsigned*)&l0; w2l[kc][1] = *(unsigned*)&l1;
    }
    const float bias2 = __ldg(b2);
    const int is64 = g_is64;
    const __half2 zero2 = __float2half2_rn(0.f);

    // ---- gather + relu -> H tile (2 edges per pass, 8 passes) ----
#pragma unroll
    for (int p = 0; p < 8; ++p) {
        const int e = wbase + p * 2 + hi16;
        if (e < E) {
            unsigned s, d;
            if (is64) {
                const long long* ei = (const long long*)ei_raw;
                s = (unsigned)ei[e];
                d = (unsigned)ei[(size_t)E + e];
            } else {
                const int* ei = (const int*)ei_raw;
                s = (unsigned)ei[e];
                d = (unsigned)ei[(size_t)E + e];
            }
            s = min(s, (unsigned)(N - 1));
            d = min(d, (unsigned)(N - 1));

            const uint4 ar = *(const uint4*)(g_AB + (size_t)s * 256 + gl * 8);
            const uint4 br = *(const uint4*)(g_AB + (size_t)d * 256 + 128 + gl * 8);
            const unsigned* au = (const unsigned*)&ar;
            const unsigned* bu = (const unsigned*)&br;
            unsigned h[4];
#pragma unroll
            for (int i = 0; i < 4; ++i) {
                __half2 r = __hmax2(__hadd2(*(const __half2*)&au[i],
                                            *(const __half2*)&bu[i]), zero2);
                h[i] = *(unsigned*)&r;
            }
            *(uint4*)&H[(p * 2 + hi16) * HS + gl * 8] = *(uint4*)h;
        }
    }
    __syncwarp();

    // ---- mma reduction: D[16 edges x 8] accumulates over 8 k-chunks ----
    float acc[4] = {0.f, 0.f, 0.f, 0.f};
    const int arow = lane & 15, acol8 = (lane >> 4) << 3;
#pragma unroll
    for (int kc = 0; kc < 8; ++kc) {
        unsigned a[4];
        ldsm4(a, H + arow * HS + kc * 16 + acol8);
        mma16816(acc, a, w2h[kc]);
        mma16816(acc, a, w2l[kc]);
    }

    // ---- col 0 of D: lanes with lane%4==0 hold rows lane/4 and lane/4+8 ----
    if ((lane & 3) == 0) {
        const int r0 = wbase + (lane >> 2);
        const int r1 = r0 + 8;
        if (r0 < E) out[r0] = acc[0] + bias2;
        if (r1 < E) out[r1] = acc[2] + bias2;
    }
}

// ---------------------------------------------------------------------------
extern "C" void kernel_launch(void* const* d_in, const int* in_sizes, int n_in,
                              void* d_out, int out_size)
{
    const float* z   = (const float*)d_in[0];
    const void*  ei  = d_in[1];
    const float* W1  = (const float*)d_in[2];
    const float* b1  = (const float*)d_in[3];
    const float* W2  = (const float*)d_in[4];
    const float* b2  = (const float*)d_in[5];
    float*       out = (float*)d_out;

    const int N = in_sizes[0] / HID;   // 100000
    const int E = in_sizes[1] / 2;     // 1600000

    static int smem_set = 0;
    if (!smem_set) {
        cudaFuncSetAttribute(gemm_tc, cudaFuncAttributeMaxDynamicSharedMemorySize,
                             SMEM_BYTES);
        smem_set = 1;
    }

    prep_w<<<64, 512>>>(W1, (const int*)ei);

    const int nstrips = (N + MTILE - 1) / MTILE;       // 1563
    gemm_tc<<<296, 512, SMEM_BYTES>>>(z, b1, N, nstrips);

    // 8 warps x 16 edges = 128 edges/block
    edge_score<<<(E + 127) / 128, 256>>>(ei, W2, b2, out, E, N);
}